// round 13
// baseline (speedup 1.0000x reference)
#include <cuda_runtime.h>
#include <cuda_fp16.h>
#include <math.h>
#include <stdint.h>

// Problem constants
#define TT 1024
#define DD 192
#define NHH 4
#define NN 3072
#define VV 256
#define NLAYER 4
#define KSPLIT 16
#define KCH ((NHH*NN)/KSPLIT)   // 768
#define NSTAGE 3
#define BK 64
#define SROWH 72                 // halves per smem row (64 + 8 pad), K1
#define ST1_H (128*SROWH)
#define SROW2 200                // halves per smem row (192 + 8 pad), wide
#define WA_H (128*SROW2)
#define WB_H (256*SROW2)
#define SCSPLIT 4

// ---------------------------------------------------------------------------
// Static device scratch -- 16B aligned for cp.async
// ---------------------------------------------------------------------------
__device__ __align__(16) float   g_x[TT*DD];        // fp32 residual chain
__device__ __align__(16) __half  g_xr[TT*DD];       // fp16 copy (GEMM A)
__device__ __align__(16) __half  g_xT[DD*TT];       // fp16 x^T (GEMM B for ykv)
__device__ __align__(16) __half  g_xs[NHH*TT*NN];   // fp16 x_sparse (elementwise)
__device__ __align__(16) __half  g_qr[NHH*TT*NN];   // fp16 qr; reused as xy
__device__ __align__(16) __half  g_sc[NHH*TT*TT];   // fp16 masked scores (upper: static 0)
__device__ __align__(16) float   g_scp[SCSPLIT*NHH*TT*TT];// scores split-K partials
__device__ __align__(16) __half  g_ykv[NHH*TT*DD];  // fp16 after ln
__device__ __align__(16) float   g_part[KSPLIT*TT*DD];
__device__ __align__(16) float2  g_rt[TT*(NN/2)];
__device__ __align__(16) __half  g_wdxT[NHH*NN*DD];
__device__ __align__(16) __half  g_wdyT[NHH*NN*DD];
__device__ __align__(16) __half  g_encT[DD*NHH*NN];
__device__ __align__(16) __half  g_lmhT[VV*DD];

__device__ __forceinline__ uint32_t su32(const void* p) {
    uint32_t a;
    asm("{ .reg .u64 t; cvta.to.shared.u64 t, %1; cvt.u32.u64 %0, t; }"
        : "=r"(a) : "l"(p));
    return a;
}
__device__ __forceinline__ void cp16(uint32_t dst, const void* src, bool full) {
    int sz = full ? 16 : 0;
    asm volatile("cp.async.cg.shared.global [%0], [%1], 16, %2;"
                 :: "r"(dst), "l"(src), "r"(sz) : "memory");
}
__device__ __forceinline__ void mma16(float c[4], const uint32_t a[4], const uint32_t b[2]) {
    asm volatile(
        "mma.sync.aligned.m16n8k16.row.col.f32.f16.f16.f32 "
        "{%0,%1,%2,%3}, {%4,%5,%6,%7}, {%8,%9}, {%0,%1,%2,%3};"
        : "+f"(c[0]), "+f"(c[1]), "+f"(c[2]), "+f"(c[3])
        : "r"(a[0]), "r"(a[1]), "r"(a[2]), "r"(a[3]), "r"(b[0]), "r"(b[1]));
}
__device__ __forceinline__ void ldsm4(uint32_t d[4], uint32_t addr) {
    asm volatile("ldmatrix.sync.aligned.m8n8.x4.shared.b16 {%0,%1,%2,%3}, [%4];"
                 : "=r"(d[0]), "=r"(d[1]), "=r"(d[2]), "=r"(d[3]) : "r"(addr));
}
__device__ __forceinline__ uint32_t packh2(float a, float b) {
    __half2 h = __floats2half2_rn(a, b);
    return *(uint32_t*)&h;
}
__device__ __forceinline__ float2 unpackh2(uint32_t u) {
    __half2 h = *(__half2*)&u;
    return __half22float2(h);
}
__device__ __forceinline__ __half h1(float a) { return __float2half_rn(a); }

// ---------------------------------------------------------------------------
// Kernel 1: tile 128x128, 256 thr (8 warps 4m x 2n), fp16 in, fp32 out.
// C[M,Nc] = A[M,K] @ B[Nc,K]^T
// AZM: 0 normal | 1 ymlp split-K | 2 ykv tri-skip split-K | 3 scores tri + K-split4
// ---------------------------------------------------------------------------
template<int AZM>
__global__ __launch_bounds__(256, 2)
void gemm_mma(const __half* __restrict__ A, const __half* __restrict__ B,
              float* __restrict__ C,
              int Nc, int K, int lda, int ldb, int ldc,
              long long sA, long long sB, long long sC)
{
    extern __shared__ __half smh[];
    const uint32_t sA_u = su32(smh);
    const uint32_t sB_u = su32(smh + NSTAGE * ST1_H);

    const int bx = blockIdx.x, by = blockIdx.y, bz = blockIdx.z;
    const int tid = threadIdx.x;
    const int wid = tid >> 5, lane = tid & 31;
    const int grp = lane >> 2, qid = lane & 3;
    const int wm0 = (wid & 3) * 32, wn0 = (wid >> 2) * 64;

    int row0, col0 = bx * 128;
    int koff = 0;
    if (AZM == 3) {
        int bid = bx;
        int by3 = (int)((sqrtf(8.f * bid + 1.f) - 1.f) * 0.5f);
        while ((by3 + 1) * (by3 + 2) / 2 <= bid) by3++;
        while (by3 * (by3 + 1) / 2 > bid)       by3--;
        row0 = by3 * 128;
        col0 = (bid - by3 * (by3 + 1) / 2) * 128;
        long long hoff = (long long)(bz >> 2) * sA + (long long)(bz & 3) * K;
        A += hoff; B += hoff;
        C += (long long)bz * sC;
    } else if (AZM == 2) {
        // bz = h*20 + j; decode j -> (by2, kz) with kz <= by2/2
        int h = bz / 20, j = bz - h * 20;
        int by2 = 0, c0 = 0;
        #pragma unroll 8
        for (int q = 0; q < 8; q++) {
            int cnt = (by2 >> 1) + 1;
            if (j < c0 + cnt) break;
            c0 += cnt; by2++;
        }
        int kz = j - c0;
        row0 = by2 * 128;
        A += (long long)h * sA + kz * 256;
        B += kz * 256;
        C += (long long)(h * 4 + kz) * sC;
    } else if (AZM == 1) {
        row0 = by * 128;
        koff = bz * KCH;
        B += (long long)bz * sB;
        C += (long long)bz * sC;
    } else {
        row0 = by * 128;
        A += (long long)bz * sA;
        B += (long long)bz * sB;
        C += (long long)bz * sC;
    }

    const int rowA = (lane & 7) + ((lane >> 3) & 1) * 8;
    const int kA   = ((lane >> 4) & 1) * 8;
    const int rowB = (lane & 7) + ((lane >> 4) & 1) * 8;
    const int kB   = ((lane >> 3) & 1) * 8;
    const uint32_t aBase = sA_u + 2u * ((wm0 + rowA) * SROWH + kA);
    const uint32_t bBase = sB_u + 2u * ((wn0 + rowB) * SROWH + kB);

    float acc[2][8][4];
    #pragma unroll
    for (int mi = 0; mi < 2; mi++)
        #pragma unroll
        for (int ni = 0; ni < 8; ni++)
            #pragma unroll
            for (int j = 0; j < 4; j++) acc[mi][ni][j] = 0.f;

    const int nch = K / BK;

    auto issue = [&](int s) {
        const int k0 = s * BK;
        const int buf = s % NSTAGE;
        #pragma unroll
        for (int it = 0; it < 4; it++) {
            int idx = tid + it * 256;
            int r = idx >> 3, kc = (idx & 7) << 3;
            const __half* src;
            if (AZM == 1) {
                int gk = koff + k0 + kc;
                int hh = gk / NN, nn = gk - hh * NN;
                src = A + (size_t)hh * TT * NN + (size_t)(row0 + r) * lda + nn;
            } else {
                src = A + (size_t)(row0 + r) * lda + k0 + kc;
            }
            cp16(sA_u + (buf * ST1_H + r * SROWH + kc) * 2, src, true);
        }
        #pragma unroll
        for (int it = 0; it < 4; it++) {
            int idx = tid + it * 256;
            int nr = idx >> 3, kc = (idx & 7) << 3;
            const __half* src = B + (size_t)(col0 + nr) * ldb + k0 + kc;
            cp16(sB_u + (buf * ST1_H + nr * SROWH + kc) * 2, src, col0 + nr < Nc);
        }
        asm volatile("cp.async.commit_group;" ::: "memory");
    };

    #pragma unroll
    for (int s = 0; s < NSTAGE - 1; s++) issue(s);

    for (int c = 0; c < nch; c++) {
        asm volatile("cp.async.wait_group %0;" :: "n"(NSTAGE - 2) : "memory");
        __syncthreads();
        if (c + NSTAGE - 1 < nch) issue(c + NSTAGE - 1);

        const int buf = c % NSTAGE;
        const uint32_t aOff = aBase + 2u * buf * ST1_H;
        const uint32_t bOff = bBase + 2u * buf * ST1_H;
        #pragma unroll
        for (int ks = 0; ks < BK; ks += 16) {
            uint32_t af[2][4], bf8[8][2];
            #pragma unroll
            for (int mi = 0; mi < 2; mi++)
                ldsm4(af[mi], aOff + 2u * (mi * 16 * SROWH + ks));
            #pragma unroll
            for (int p = 0; p < 4; p++) {
                uint32_t t4[4];
                ldsm4(t4, bOff + 2u * (p * 16 * SROWH + ks));
                bf8[2 * p    ][0] = t4[0]; bf8[2 * p    ][1] = t4[1];
                bf8[2 * p + 1][0] = t4[2]; bf8[2 * p + 1][1] = t4[3];
            }
            #pragma unroll
            for (int mi = 0; mi < 2; mi++)
                #pragma unroll
                for (int ni = 0; ni < 8; ni++)
                    mma16(acc[mi][ni], af[mi], bf8[ni]);
        }
    }

    #pragma unroll
    for (int mi = 0; mi < 2; mi++) {
        const int rA = row0 + wm0 + mi * 16 + grp;
        const int rB = rA + 8;
        #pragma unroll
        for (int ni = 0; ni < 8; ni++) {
            const int c = col0 + wn0 + ni * 8 + (qid << 1);
            if (c >= Nc) continue;
            *(float2*)(C + (size_t)rA * ldc + c) = make_float2(acc[mi][ni][0], acc[mi][ni][1]);
            *(float2*)(C + (size_t)rB * ldc + c) = make_float2(acc[mi][ni][2], acc[mi][ni][3]);
        }
    }
}

// ---------------------------------------------------------------------------
// Kernel 2: wide single-shot GEMM. K=192 (fits entirely in smem).
// Tile 128x256, 512 thr (16 warps 4m x 4n). One load, one sync, no pipeline.
// EPI 1: xs fp16 = relu(acc); qr fp16 = rope(fp32 relu) -> auxp
// EPI 2: xy fp16 = relu(acc)*xs(fp16 auxp, fp32 math)
// ---------------------------------------------------------------------------
template<int EPI>
__global__ __launch_bounds__(512, 1)
void gemm_wide(const __half* __restrict__ A, const __half* __restrict__ B,
               void* __restrict__ Cv, void* __restrict__ auxp,
               const float2* __restrict__ rtab,
               long long sA, long long sB, long long sC, long long sAux)
{
    extern __shared__ __half smh[];
    const uint32_t sA_u = su32(smh);
    const uint32_t sB_u = su32(smh + WA_H);

    const int bx = blockIdx.x, by = blockIdx.y, bz = blockIdx.z;
    const int tid = threadIdx.x;
    const int wid = tid >> 5, lane = tid & 31;
    const int grp = lane >> 2, qid = lane & 3;
    const int wm0 = (wid & 3) * 32, wn0 = (wid >> 2) * 64;
    const int row0 = by * 128, col0 = bx * 256;

    A += (long long)bz * sA;
    B += (long long)bz * sB;

    #pragma unroll
    for (int it = 0; it < 6; it++) {
        int idx = tid + it * 512;
        int r = idx / 24, kc = (idx % 24) << 3;
        cp16(sA_u + (r * SROW2 + kc) * 2,
             A + (size_t)(row0 + r) * DD + kc, true);
    }
    #pragma unroll
    for (int it = 0; it < 12; it++) {
        int idx = tid + it * 512;
        int nr = idx / 24, kc = (idx % 24) << 3;
        cp16(sB_u + (nr * SROW2 + kc) * 2,
             B + (size_t)(col0 + nr) * DD + kc, true);
    }
    asm volatile("cp.async.commit_group;" ::: "memory");
    asm volatile("cp.async.wait_group 0;" ::: "memory");
    __syncthreads();

    const int rowA = (lane & 7) + ((lane >> 3) & 1) * 8;
    const int kA   = ((lane >> 4) & 1) * 8;
    const int rowB = (lane & 7) + ((lane >> 4) & 1) * 8;
    const int kB   = ((lane >> 3) & 1) * 8;
    const uint32_t aBase = sA_u + 2u * ((wm0 + rowA) * SROW2 + kA);
    const uint32_t bBase = sB_u + 2u * ((wn0 + rowB) * SROW2 + kB);

    float acc[2][8][4];
    #pragma unroll
    for (int mi = 0; mi < 2; mi++)
        #pragma unroll
        for (int ni = 0; ni < 8; ni++)
            #pragma unroll
            for (int j = 0; j < 4; j++) acc[mi][ni][j] = 0.f;

    #pragma unroll
    for (int ks = 0; ks < DD; ks += 16) {
        uint32_t af[2][4], bf8[8][2];
        #pragma unroll
        for (int mi = 0; mi < 2; mi++)
            ldsm4(af[mi], aBase + 2u * (mi * 16 * SROW2 + ks));
        #pragma unroll
        for (int p = 0; p < 4; p++) {
            uint32_t t4[4];
            ldsm4(t4, bBase + 2u * (p * 16 * SROW2 + ks));
            bf8[2 * p    ][0] = t4[0]; bf8[2 * p    ][1] = t4[1];
            bf8[2 * p + 1][0] = t4[2]; bf8[2 * p + 1][1] = t4[3];
        }
        #pragma unroll
        for (int mi = 0; mi < 2; mi++)
            #pragma unroll
            for (int ni = 0; ni < 8; ni++)
                mma16(acc[mi][ni], af[mi], bf8[ni]);
    }

    // ---- epilogue ----
    #pragma unroll
    for (int mi = 0; mi < 2; mi++) {
        const int rA = row0 + wm0 + mi * 16 + grp;
        const int rB = rA + 8;
        #pragma unroll
        for (int ni = 0; ni < 8; ni++) {
            const int c = col0 + wn0 + ni * 8 + (qid << 1);
            float2 lo = make_float2(acc[mi][ni][0], acc[mi][ni][1]);
            float2 hi = make_float2(acc[mi][ni][2], acc[mi][ni][3]);
            if (EPI == 1) {
                __half* Cx = (__half*)Cv + (long long)bz * sC;
                __half* Q = (__half*)auxp + (long long)bz * sAux;
                lo.x = fmaxf(lo.x, 0.f); lo.y = fmaxf(lo.y, 0.f);
                hi.x = fmaxf(hi.x, 0.f); hi.y = fmaxf(hi.y, 0.f);
                *(uint32_t*)(Cx + (size_t)rA * NN + c) = packh2(lo.x, lo.y);
                *(uint32_t*)(Cx + (size_t)rB * NN + c) = packh2(hi.x, hi.y);
                float2 ca = rtab[(size_t)rA * (NN / 2) + (c >> 1)];
                float2 cb = rtab[(size_t)rB * (NN / 2) + (c >> 1)];
                *(uint32_t*)(Q + (size_t)rA * NN + c) =
                    packh2(lo.x * ca.x - lo.y * ca.y, lo.y * ca.x + lo.x * ca.y);
                *(uint32_t*)(Q + (size_t)rB * NN + c) =
                    packh2(hi.x * cb.x - hi.y * cb.y, hi.y * cb.x + hi.x * cb.y);
            } else { // EPI == 2
                __half* Cx = (__half*)Cv + (long long)bz * sC;
                const __half* E = (const __half*)auxp + (long long)bz * sAux;
                float2 ea = unpackh2(*(const uint32_t*)(E + (size_t)rA * NN + c));
                float2 eb = unpackh2(*(const uint32_t*)(E + (size_t)rB * NN + c));
                *(uint32_t*)(Cx + (size_t)rA * NN + c) =
                    packh2(fmaxf(lo.x, 0.f) * ea.x, fmaxf(lo.y, 0.f) * ea.y);
                *(uint32_t*)(Cx + (size_t)rB * NN + c) =
                    packh2(fmaxf(hi.x, 0.f) * eb.x, fmaxf(hi.y, 0.f) * eb.y);
            }
        }
    }
}

// ---------------------------------------------------------------------------
// scores reduce: g_sc(fp16) = tril_mask(p0+p1+p2+p3); upper triangle statically 0
// ---------------------------------------------------------------------------
__global__ void reduce_sc_k()
{
    int idx = blockIdx.x * 256 + threadIdx.x;          // 8-col units
    int c  = (idx & (TT / 8 - 1)) << 3;
    int r  = (idx >> 7) & (TT - 1);
    int h  = idx >> 17;
    if (c >= r) return;
    uint4 o;
    size_t base = (size_t)(h * SCSPLIT) * TT * TT + (size_t)r * TT + c;
    const size_t str = (size_t)TT * TT;
    if (c + 7 < r) {
        float v[8];
        #pragma unroll
        for (int j = 0; j < 8; j++) v[j] = 0.f;
        #pragma unroll
        for (int q = 0; q < SCSPLIT; q++) {
            float4 a0 = *(const float4*)(g_scp + base + q * str);
            float4 a1 = *(const float4*)(g_scp + base + q * str + 4);
            v[0] += a0.x; v[1] += a0.y; v[2] += a0.z; v[3] += a0.w;
            v[4] += a1.x; v[5] += a1.y; v[6] += a1.z; v[7] += a1.w;
        }
        o.x = packh2(v[0], v[1]); o.y = packh2(v[2], v[3]);
        o.z = packh2(v[4], v[5]); o.w = packh2(v[6], v[7]);
    } else {
        float v[8];
        #pragma unroll
        for (int j = 0; j < 8; j++) {
            float s = 0.f;
            if (c + j < r)
                #pragma unroll
                for (int q = 0; q < SCSPLIT; q++) s += g_scp[base + q * str + j];
            v[j] = s;
        }
        o.x = packh2(v[0], v[1]); o.y = packh2(v[2], v[3]);
        o.z = packh2(v[4], v[5]); o.w = packh2(v[6], v[7]);
    }
    *(uint4*)(g_sc + (size_t)h * TT * TT + (size_t)r * TT + c) = o;
}

// ---------------------------------------------------------------------------
__global__ void transpose_half_k(const float* __restrict__ in, __half* __restrict__ out,
                                 int M, int Nn, long long inS, long long outS)
{
    __shared__ float t[32][33];
    in  += (long long)blockIdx.z * inS;
    out += (long long)blockIdx.z * outS;
    int x = blockIdx.x * 32 + threadIdx.x;
    int y = blockIdx.y * 32 + threadIdx.y;
    #pragma unroll
    for (int i = 0; i < 32; i += 8)
        t[threadIdx.y + i][threadIdx.x] = in[(size_t)(y + i) * Nn + x];
    __syncthreads();
    int x2 = blockIdx.y * 32 + threadIdx.x;
    int y2 = blockIdx.x * 32 + threadIdx.y;
    #pragma unroll
    for (int i = 0; i < 32; i += 8)
        out[(size_t)(y2 + i) * M + x2] = h1(t[threadIdx.x][threadIdx.y + i]);
}

// ---------------------------------------------------------------------------
__device__ __forceinline__ float2 meanvar192(float v, float* s1, float* s2)
{
    __syncthreads();
    float a = v, b = v * v;
    #pragma unroll
    for (int o = 16; o > 0; o >>= 1) {
        a += __shfl_down_sync(0xffffffffu, a, o);
        b += __shfl_down_sync(0xffffffffu, b, o);
    }
    int lane = threadIdx.x & 31, w = threadIdx.x >> 5;
    if (lane == 0) { s1[w] = a; s2[w] = b; }
    __syncthreads();
    if (threadIdx.x == 0) {
        float sa = 0.f, sb = 0.f;
        #pragma unroll
        for (int i = 0; i < 6; i++) { sa += s1[i]; sb += s2[i]; }
        s1[0] = sa; s2[0] = sb;
    }
    __syncthreads();
    float m   = s1[0] * (1.0f / 192.0f);
    float var = s2[0] * (1.0f / 192.0f) - m * m;
    return make_float2(m, fmaxf(var, 0.f));
}

__global__ void embed_ln_k(const int* __restrict__ idx,
                           const float* __restrict__ emb,
                           const float* __restrict__ pos)
{
    int t = blockIdx.x, d = threadIdx.x;
    __shared__ float s1[8], s2[8];
    float v = emb[(size_t)idx[t] * DD + d] + pos[(size_t)t * DD + d];
    float2 mv = meanvar192(v, s1, s2);
    float r = (v - mv.x) * rsqrtf(mv.y + 1e-5f);
    g_x [(size_t)t * DD + d] = r;
    g_xr[(size_t)t * DD + d] = h1(r);
    g_xT[(size_t)d * TT + t] = h1(r);
}

__global__ void sincos_k()
{
    int i = blockIdx.x * blockDim.x + threadIdx.x;
    if (i >= TT * (NN / 2)) return;
    int t = i / (NN / 2);
    int p = i - t * (NN / 2);
    float f = exp2f(-(float)p * (1.0f / 96.0f)) * 0.15915494309189535f;
    float tf = (float)t * f;
    float ph = (tf - floorf(tf)) * 6.283185307179586f;
    float s, c;
    __sincosf(ph, &s, &c);
    g_rt[i] = make_float2(c, s);
}

// ykv: reduce valid split-K partials only (kz <= t>>8), then LN -> fp16
__global__ void ln_ykv_k()
{
    int r = blockIdx.x, d = threadIdx.x;     // r = h*TT + t
    __shared__ float s1[8], s2[8];
    int h = r >> 10, t = r & (TT - 1);
    int kcnt = (t >> 8) + 1;
    float v = 0.f;
    for (int kz = 0; kz < kcnt; kz++)
        v += g_part[(size_t)(h * 4 + kz) * TT * DD + (size_t)t * DD + d];
    float2 mv = meanvar192(v, s1, s2);
    g_ykv[(size_t)r * DD + d] = h1((v - mv.x) * rsqrtf(mv.y + 1e-5f));
}

__global__ void finalize_k()
{
    int t = blockIdx.x, d = threadIdx.x;
    __shared__ float s1[8], s2[8];
    float ym = 0.f;
    #pragma unroll
    for (int c = 0; c < KSPLIT; c++)
        ym += g_part[(size_t)c * TT * DD + (size_t)t * DD + d];
    float2 mv = meanvar192(ym, s1, s2);
    float l1 = (ym - mv.x) * rsqrtf(mv.y + 1e-5f);
    float xv = g_x[(size_t)t * DD + d] + l1;
    float2 mv2 = meanvar192(xv, s1, s2);
    float r = (xv - mv2.x) * rsqrtf(mv2.y + 1e-5f);
    g_x [(size_t)t * DD + d] = r;
    g_xr[(size_t)t * DD + d] = h1(r);
    g_xT[(size_t)d * TT + t] = h1(r);
}

// ---------------------------------------------------------------------------
extern "C" void kernel_launch(void* const* d_in, const int* in_sizes, int n_in,
                              void* d_out, int out_size)
{
    const int*   idx  = (const int*)  d_in[0];
    const float* decx = (const float*)d_in[1];
    const float* decy = (const float*)d_in[2];
    const float* enc  = (const float*)d_in[3];
    const float* emb  = (const float*)d_in[4];
    const float* pos  = (const float*)d_in[5];
    const float* lmh  = (const float*)d_in[6];
    float* out = (float*)d_out;

    __half *pxr, *pxT, *pxs, *pqr, *psc, *pykv, *pwdxT, *pwdyT, *pencT, *plmhT;
    float *pscp, *ppart;
    float2* prt;
    cudaGetSymbolAddress((void**)&pxr,   g_xr);
    cudaGetSymbolAddress((void**)&pxT,   g_xT);
    cudaGetSymbolAddress((void**)&pxs,   g_xs);
    cudaGetSymbolAddress((void**)&pqr,   g_qr);
    cudaGetSymbolAddress((void**)&psc,   g_sc);
    cudaGetSymbolAddress((void**)&pscp,  g_scp);
    cudaGetSymbolAddress((void**)&pykv,  g_ykv);
    cudaGetSymbolAddress((void**)&ppart, g_part);
    cudaGetSymbolAddress((void**)&prt,   g_rt);
    cudaGetSymbolAddress((void**)&pwdxT, g_wdxT);
    cudaGetSymbolAddress((void**)&pwdyT, g_wdyT);
    cudaGetSymbolAddress((void**)&pencT, g_encT);
    cudaGetSymbolAddress((void**)&plmhT, g_lmhT);

    const int SMEM1 = NSTAGE * 2 * ST1_H * 2;            // 110592 B
    const int SMEMW = (WA_H + WB_H) * 2;                 // 153600 B
    cudaFuncSetAttribute(gemm_mma<0>,  cudaFuncAttributeMaxDynamicSharedMemorySize, SMEM1);
    cudaFuncSetAttribute(gemm_mma<1>,  cudaFuncAttributeMaxDynamicSharedMemorySize, SMEM1);
    cudaFuncSetAttribute(gemm_mma<2>,  cudaFuncAttributeMaxDynamicSharedMemorySize, SMEM1);
    cudaFuncSetAttribute(gemm_mma<3>,  cudaFuncAttributeMaxDynamicSharedMemorySize, SMEM1);
    cudaFuncSetAttribute(gemm_wide<1>, cudaFuncAttributeMaxDynamicSharedMemorySize, SMEMW);
    cudaFuncSetAttribute(gemm_wide<2>, cudaFuncAttributeMaxDynamicSharedMemorySize, SMEMW);

    dim3 tb(32, 8);
    transpose_half_k<<<dim3(NN/32, DD/32, NHH), tb>>>(decx, pwdxT, DD, NN,
                                                      (long long)DD*NN, (long long)NN*DD);
    transpose_half_k<<<dim3(NN/32, DD/32, NHH), tb>>>(decy, pwdyT, DD, NN,
                                                      (long long)DD*NN, (long long)NN*DD);
    transpose_half_k<<<dim3(DD/32, (NHH*NN)/32, 1), tb>>>(enc, pencT, NHH*NN, DD, 0, 0);
    transpose_half_k<<<dim3(VV/32, DD/32, 1), tb>>>(lmh, plmhT, DD, VV, 0, 0);

    sincos_k<<<(TT * (NN / 2) + 255) / 256, 256>>>();
    embed_ln_k<<<TT, 192>>>(idx, emb, pos);

    for (int l = 0; l < NLAYER; l++) {
        // x_sparse(fp16) = relu(x @ decx[h]);  qr(fp16) = rope(fp32 relu)
        gemm_wide<1><<<dim3(NN / 256, TT / 128, NHH), 512, SMEMW>>>(
            pxr, pwdxT, pxs, pqr, prt,
            0LL, (long long)NN * DD, (long long)TT * NN, (long long)TT * NN);

        // scores partials: lower-triangle tiles, K split in 4 (bz = h*4+ks)
        gemm_mma<3><<<dim3(36, 1, NHH * SCSPLIT), 256, SMEM1>>>(
            pqr, pqr, pscp, TT, NN / SCSPLIT, NN, NN, TT,
            (long long)TT * NN, 0LL, (long long)TT * TT);

        // g_sc(fp16) = tril_mask(sum partials) [lower triangle only]
        reduce_sc_k<<<NHH * TT * TT / 8 / 256, 256>>>();

        // ykv partials(fp32) = scores @ x   (tri-skip split-K; bz = h*20+j)
        gemm_mma<2><<<dim3(2, 1, NHH * 20), 256, SMEM1>>>(
            psc, pxT, ppart, DD, 256, TT, TT, DD,
            (long long)TT * TT, 0LL, (long long)TT * DD);

        // ykv(fp16) = ln(sum valid partials)
        ln_ykv_k<<<NHH * TT, 192>>>();

        // xy(fp16) = relu(ykv @ decy[h]) * x_sparse(fp16, fp32 math)
        gemm_wide<2><<<dim3(NN / 256, TT / 128, NHH), 512, SMEMW>>>(
            pykv, pwdyT, pqr, pxs, nullptr,
            (long long)TT * DD, (long long)NN * DD, (long long)TT * NN,
            (long long)TT * NN);

        // ymlp partials(fp32): xy @ enc^T, split-K = 16
        gemm_mma<1><<<dim3(2, TT / 128, KSPLIT), 256, SMEM1>>>(
            pqr, pencT, ppart, DD, KCH, NN, NHH * NN, DD,
            0LL, (long long)KCH, (long long)TT * DD);

        finalize_k<<<TT, 192>>>();
    }

    // logits(fp32) = x @ lm_head
    gemm_mma<0><<<dim3(2, TT / 128, 1), 256, SMEM1>>>(
        pxr, plmhT, out, VV, DD, DD, DD, VV,
        0LL, 0LL, 0LL);
}

// round 14
// speedup vs baseline: 1.0428x; 1.0428x over previous
#include <cuda_runtime.h>
#include <cuda_fp16.h>
#include <math.h>
#include <stdint.h>

// Problem constants
#define TT 1024
#define DD 192
#define NHH 4
#define NN 3072
#define VV 256
#define NLAYER 4
#define KSPLIT 16
#define KCH ((NHH*NN)/KSPLIT)   // 768
#define NSTAGE 3
#define BK 64
#define SROWH 72                 // halves per smem row (64 + 8 pad)
#define ST1_H (128*SROWH)
#define SCSPLIT 2

// ---------------------------------------------------------------------------
// Static device scratch -- 16B aligned for cp.async
// ---------------------------------------------------------------------------
__device__ __align__(16) float   g_x[TT*DD];        // fp32 residual chain
__device__ __align__(16) __half  g_xr[TT*DD];       // fp16 copy (GEMM A)
__device__ __align__(16) __half  g_xT[DD*TT];       // fp16 x^T (GEMM B for ykv)
__device__ __align__(16) __half  g_xs[NHH*TT*NN];   // fp16 x_sparse (elementwise)
__device__ __align__(16) __half  g_qr[NHH*TT*NN];   // fp16 qr; reused as xy
__device__ __align__(16) __half  g_sc[NHH*TT*TT];   // fp16 masked scores (upper: static 0)
__device__ __align__(16) float   g_scp[SCSPLIT*NHH*TT*TT];// scores split-K partials
__device__ __align__(16) __half  g_ykv[NHH*TT*DD];  // fp16 after ln
__device__ __align__(16) float   g_part[KSPLIT*TT*DD];
__device__ __align__(16) float2  g_rt[TT*(NN/2)];
__device__ __align__(16) __half  g_wdxT[NHH*NN*DD];
__device__ __align__(16) __half  g_wdyT[NHH*NN*DD];
__device__ __align__(16) __half  g_encT[DD*NHH*NN];
__device__ __align__(16) __half  g_lmhT[VV*DD];

__device__ __forceinline__ uint32_t su32(const void* p) {
    uint32_t a;
    asm("{ .reg .u64 t; cvta.to.shared.u64 t, %1; cvt.u32.u64 %0, t; }"
        : "=r"(a) : "l"(p));
    return a;
}
__device__ __forceinline__ void cp16(uint32_t dst, const void* src, bool full) {
    int sz = full ? 16 : 0;
    asm volatile("cp.async.cg.shared.global [%0], [%1], 16, %2;"
                 :: "r"(dst), "l"(src), "r"(sz) : "memory");
}
__device__ __forceinline__ void mma16(float c[4], const uint32_t a[4], const uint32_t b[2]) {
    asm volatile(
        "mma.sync.aligned.m16n8k16.row.col.f32.f16.f16.f32 "
        "{%0,%1,%2,%3}, {%4,%5,%6,%7}, {%8,%9}, {%0,%1,%2,%3};"
        : "+f"(c[0]), "+f"(c[1]), "+f"(c[2]), "+f"(c[3])
        : "r"(a[0]), "r"(a[1]), "r"(a[2]), "r"(a[3]), "r"(b[0]), "r"(b[1]));
}
__device__ __forceinline__ void ldsm4(uint32_t d[4], uint32_t addr) {
    asm volatile("ldmatrix.sync.aligned.m8n8.x4.shared.b16 {%0,%1,%2,%3}, [%4];"
                 : "=r"(d[0]), "=r"(d[1]), "=r"(d[2]), "=r"(d[3]) : "r"(addr));
}
__device__ __forceinline__ uint32_t packh2(float a, float b) {
    __half2 h = __floats2half2_rn(a, b);
    return *(uint32_t*)&h;
}
__device__ __forceinline__ float2 unpackh2(uint32_t u) {
    __half2 h = *(__half2*)&u;
    return __half22float2(h);
}
__device__ __forceinline__ __half h1(float a) { return __float2half_rn(a); }

// ---------------------------------------------------------------------------
// Unified GEMM: tile 128x128, 256 thr (8 warps 4m x 2n), fp16 in, cp.async
// 3-stage pipeline, ldmatrix fragments.  C-ish[M,Nc] = epi(A[M,K] @ B[Nc,K]^T)
// AZM: 0 plain fp32 (logits) | 1 ymlp split-K fp32 | 2 ykv tri-skip fp32 |
//      3 scores tri + K-split2 fp32 |
//      4 x_sparse: xs(fp16)=relu, qr(fp16)=rope(relu) | 5 xy(fp16)=relu*xs
// ---------------------------------------------------------------------------
template<int AZM>
__global__ __launch_bounds__(256, 2)
void gemm_mma(const __half* __restrict__ A, const __half* __restrict__ B,
              void* __restrict__ Cv, const __half* __restrict__ aux,
              __half* __restrict__ aux2, const float2* __restrict__ rtab,
              int Nc, int K, int lda, int ldb, int ldc,
              long long sA, long long sB, long long sC)
{
    extern __shared__ __half smh[];
    const uint32_t sA_u = su32(smh);
    const uint32_t sB_u = su32(smh + NSTAGE * ST1_H);

    const int bx = blockIdx.x, by = blockIdx.y, bz = blockIdx.z;
    const int tid = threadIdx.x;
    const int wid = tid >> 5, lane = tid & 31;
    const int grp = lane >> 2, qid = lane & 3;
    const int wm0 = (wid & 3) * 32, wn0 = (wid >> 2) * 64;

    int row0, col0 = bx * 128;
    int koff = 0;
    float* Cf = (float*)Cv;
    if (AZM == 3) {
        int bid = bx;
        int by3 = (int)((sqrtf(8.f * bid + 1.f) - 1.f) * 0.5f);
        while ((by3 + 1) * (by3 + 2) / 2 <= bid) by3++;
        while (by3 * (by3 + 1) / 2 > bid)       by3--;
        row0 = by3 * 128;
        col0 = (bid - by3 * (by3 + 1) / 2) * 128;
        long long hoff = (long long)(bz >> 1) * sA + (long long)(bz & 1) * K;
        A += hoff; B += hoff;
        Cf += (long long)bz * sC;
    } else if (AZM == 2) {
        // bz = h*20 + j; decode j -> (by2, kz) with kz <= by2/2
        int h = bz / 20, j = bz - h * 20;
        int by2 = 0, c0 = 0;
        #pragma unroll 8
        for (int q = 0; q < 8; q++) {
            int cnt = (by2 >> 1) + 1;
            if (j < c0 + cnt) break;
            c0 += cnt; by2++;
        }
        int kz = j - c0;
        row0 = by2 * 128;
        A += (long long)h * sA + kz * 256;
        B += kz * 256;
        Cf += (long long)(h * 4 + kz) * sC;
    } else if (AZM == 1) {
        row0 = by * 128;
        koff = bz * KCH;
        B += (long long)bz * sB;
        Cf += (long long)bz * sC;
    } else {
        row0 = by * 128;
        A += (long long)bz * sA;
        B += (long long)bz * sB;
        if (AZM == 0) Cf += (long long)bz * sC;
    }

    const int rowA = (lane & 7) + ((lane >> 3) & 1) * 8;
    const int kA   = ((lane >> 4) & 1) * 8;
    const int rowB = (lane & 7) + ((lane >> 4) & 1) * 8;
    const int kB   = ((lane >> 3) & 1) * 8;
    const uint32_t aBase = sA_u + 2u * ((wm0 + rowA) * SROWH + kA);
    const uint32_t bBase = sB_u + 2u * ((wn0 + rowB) * SROWH + kB);

    float acc[2][8][4];
    #pragma unroll
    for (int mi = 0; mi < 2; mi++)
        #pragma unroll
        for (int ni = 0; ni < 8; ni++)
            #pragma unroll
            for (int j = 0; j < 4; j++) acc[mi][ni][j] = 0.f;

    const int nch = K / BK;

    auto issue = [&](int s) {
        const int k0 = s * BK;
        const int buf = s % NSTAGE;
        #pragma unroll
        for (int it = 0; it < 4; it++) {
            int idx = tid + it * 256;
            int r = idx >> 3, kc = (idx & 7) << 3;
            const __half* src;
            if (AZM == 1) {
                int gk = koff + k0 + kc;
                int hh = gk / NN, nn = gk - hh * NN;
                src = A + (size_t)hh * TT * NN + (size_t)(row0 + r) * lda + nn;
            } else {
                src = A + (size_t)(row0 + r) * lda + k0 + kc;
            }
            cp16(sA_u + (buf * ST1_H + r * SROWH + kc) * 2, src, true);
        }
        #pragma unroll
        for (int it = 0; it < 4; it++) {
            int idx = tid + it * 256;
            int nr = idx >> 3, kc = (idx & 7) << 3;
            const __half* src = B + (size_t)(col0 + nr) * ldb + k0 + kc;
            cp16(sB_u + (buf * ST1_H + nr * SROWH + kc) * 2, src, col0 + nr < Nc);
        }
        asm volatile("cp.async.commit_group;" ::: "memory");
    };

    #pragma unroll
    for (int s = 0; s < NSTAGE - 1; s++) issue(s);

    for (int c = 0; c < nch; c++) {
        asm volatile("cp.async.wait_group %0;" :: "n"(NSTAGE - 2) : "memory");
        __syncthreads();
        if (c + NSTAGE - 1 < nch) issue(c + NSTAGE - 1);

        const int buf = c % NSTAGE;
        const uint32_t aOff = aBase + 2u * buf * ST1_H;
        const uint32_t bOff = bBase + 2u * buf * ST1_H;
        #pragma unroll
        for (int ks = 0; ks < BK; ks += 16) {
            uint32_t af[2][4], bf8[8][2];
            #pragma unroll
            for (int mi = 0; mi < 2; mi++)
                ldsm4(af[mi], aOff + 2u * (mi * 16 * SROWH + ks));
            #pragma unroll
            for (int p = 0; p < 4; p++) {
                uint32_t t4[4];
                ldsm4(t4, bOff + 2u * (p * 16 * SROWH + ks));
                bf8[2 * p    ][0] = t4[0]; bf8[2 * p    ][1] = t4[1];
                bf8[2 * p + 1][0] = t4[2]; bf8[2 * p + 1][1] = t4[3];
            }
            #pragma unroll
            for (int mi = 0; mi < 2; mi++)
                #pragma unroll
                for (int ni = 0; ni < 8; ni++)
                    mma16(acc[mi][ni], af[mi], bf8[ni]);
        }
    }

    // ---- epilogue ----
    #pragma unroll
    for (int mi = 0; mi < 2; mi++) {
        const int rA = row0 + wm0 + mi * 16 + grp;
        const int rB = rA + 8;
        #pragma unroll
        for (int ni = 0; ni < 8; ni++) {
            const int c = col0 + wn0 + ni * 8 + (qid << 1);
            float2 lo = make_float2(acc[mi][ni][0], acc[mi][ni][1]);
            float2 hi = make_float2(acc[mi][ni][2], acc[mi][ni][3]);
            if (AZM == 4) {
                __half* Cx = (__half*)Cv + (long long)bz * sC;
                __half* Q  = aux2 + (long long)bz * sC;
                lo.x = fmaxf(lo.x, 0.f); lo.y = fmaxf(lo.y, 0.f);
                hi.x = fmaxf(hi.x, 0.f); hi.y = fmaxf(hi.y, 0.f);
                *(uint32_t*)(Cx + (size_t)rA * ldc + c) = packh2(lo.x, lo.y);
                *(uint32_t*)(Cx + (size_t)rB * ldc + c) = packh2(hi.x, hi.y);
                float2 ca = rtab[(size_t)rA * (NN / 2) + (c >> 1)];
                float2 cb = rtab[(size_t)rB * (NN / 2) + (c >> 1)];
                *(uint32_t*)(Q + (size_t)rA * ldc + c) =
                    packh2(lo.x * ca.x - lo.y * ca.y, lo.y * ca.x + lo.x * ca.y);
                *(uint32_t*)(Q + (size_t)rB * ldc + c) =
                    packh2(hi.x * cb.x - hi.y * cb.y, hi.y * cb.x + hi.x * cb.y);
            } else if (AZM == 5) {
                __half* Cx = (__half*)Cv + (long long)bz * sC;
                const __half* E = aux + (long long)bz * sC;
                float2 ea = unpackh2(*(const uint32_t*)(E + (size_t)rA * ldc + c));
                float2 eb = unpackh2(*(const uint32_t*)(E + (size_t)rB * ldc + c));
                *(uint32_t*)(Cx + (size_t)rA * ldc + c) =
                    packh2(fmaxf(lo.x, 0.f) * ea.x, fmaxf(lo.y, 0.f) * ea.y);
                *(uint32_t*)(Cx + (size_t)rB * ldc + c) =
                    packh2(fmaxf(hi.x, 0.f) * eb.x, fmaxf(hi.y, 0.f) * eb.y);
            } else {
                if (c >= Nc) continue;
                *(float2*)(Cf + (size_t)rA * ldc + c) = lo;
                *(float2*)(Cf + (size_t)rB * ldc + c) = hi;
            }
        }
    }
}

// ---------------------------------------------------------------------------
// scores reduce: g_sc(fp16) = tril_mask(p0 + p1); upper triangle statically 0
// ---------------------------------------------------------------------------
__global__ void reduce_sc_k()
{
    int idx = blockIdx.x * 256 + threadIdx.x;          // 8-col units
    int c  = (idx & (TT / 8 - 1)) << 3;
    int r  = (idx >> 7) & (TT - 1);
    int h  = idx >> 17;
    if (c >= r) return;
    uint4 o;
    size_t off  = (size_t)(h * SCSPLIT) * TT * TT + (size_t)r * TT + c;
    size_t off1 = off + (size_t)TT * TT;
    if (c + 7 < r) {
        float4 a0 = *(const float4*)(g_scp + off);
        float4 a1 = *(const float4*)(g_scp + off + 4);
        float4 b0 = *(const float4*)(g_scp + off1);
        float4 b1 = *(const float4*)(g_scp + off1 + 4);
        o.x = packh2(a0.x + b0.x, a0.y + b0.y);
        o.y = packh2(a0.z + b0.z, a0.w + b0.w);
        o.z = packh2(a1.x + b1.x, a1.y + b1.y);
        o.w = packh2(a1.z + b1.z, a1.w + b1.w);
    } else {
        float v[8];
        #pragma unroll
        for (int j = 0; j < 8; j++)
            v[j] = (c + j < r) ? (g_scp[off + j] + g_scp[off1 + j]) : 0.f;
        o.x = packh2(v[0], v[1]); o.y = packh2(v[2], v[3]);
        o.z = packh2(v[4], v[5]); o.w = packh2(v[6], v[7]);
    }
    *(uint4*)(g_sc + (size_t)h * TT * TT + (size_t)r * TT + c) = o;
}

// ---------------------------------------------------------------------------
__global__ void transpose_half_k(const float* __restrict__ in, __half* __restrict__ out,
                                 int M, int Nn, long long inS, long long outS)
{
    __shared__ float t[32][33];
    in  += (long long)blockIdx.z * inS;
    out += (long long)blockIdx.z * outS;
    int x = blockIdx.x * 32 + threadIdx.x;
    int y = blockIdx.y * 32 + threadIdx.y;
    #pragma unroll
    for (int i = 0; i < 32; i += 8)
        t[threadIdx.y + i][threadIdx.x] = in[(size_t)(y + i) * Nn + x];
    __syncthreads();
    int x2 = blockIdx.y * 32 + threadIdx.x;
    int y2 = blockIdx.x * 32 + threadIdx.y;
    #pragma unroll
    for (int i = 0; i < 32; i += 8)
        out[(size_t)(y2 + i) * M + x2] = h1(t[threadIdx.x][threadIdx.y + i]);
}

// ---------------------------------------------------------------------------
__device__ __forceinline__ float2 meanvar192(float v, float* s1, float* s2)
{
    __syncthreads();
    float a = v, b = v * v;
    #pragma unroll
    for (int o = 16; o > 0; o >>= 1) {
        a += __shfl_down_sync(0xffffffffu, a, o);
        b += __shfl_down_sync(0xffffffffu, b, o);
    }
    int lane = threadIdx.x & 31, w = threadIdx.x >> 5;
    if (lane == 0) { s1[w] = a; s2[w] = b; }
    __syncthreads();
    if (threadIdx.x == 0) {
        float sa = 0.f, sb = 0.f;
        #pragma unroll
        for (int i = 0; i < 6; i++) { sa += s1[i]; sb += s2[i]; }
        s1[0] = sa; s2[0] = sb;
    }
    __syncthreads();
    float m   = s1[0] * (1.0f / 192.0f);
    float var = s2[0] * (1.0f / 192.0f) - m * m;
    return make_float2(m, fmaxf(var, 0.f));
}

__global__ void embed_ln_k(const int* __restrict__ idx,
                           const float* __restrict__ emb,
                           const float* __restrict__ pos)
{
    int t = blockIdx.x, d = threadIdx.x;
    __shared__ float s1[8], s2[8];
    float v = emb[(size_t)idx[t] * DD + d] + pos[(size_t)t * DD + d];
    float2 mv = meanvar192(v, s1, s2);
    float r = (v - mv.x) * rsqrtf(mv.y + 1e-5f);
    g_x [(size_t)t * DD + d] = r;
    g_xr[(size_t)t * DD + d] = h1(r);
    g_xT[(size_t)d * TT + t] = h1(r);
}

__global__ void sincos_k()
{
    int i = blockIdx.x * blockDim.x + threadIdx.x;
    if (i >= TT * (NN / 2)) return;
    int t = i / (NN / 2);
    int p = i - t * (NN / 2);
    float f = exp2f(-(float)p * (1.0f / 96.0f)) * 0.15915494309189535f;
    float tf = (float)t * f;
    float ph = (tf - floorf(tf)) * 6.283185307179586f;
    float s, c;
    __sincosf(ph, &s, &c);
    g_rt[i] = make_float2(c, s);
}

// ykv: reduce valid split-K partials only (kz <= t>>8), then LN -> fp16
__global__ void ln_ykv_k()
{
    int r = blockIdx.x, d = threadIdx.x;     // r = h*TT + t
    __shared__ float s1[8], s2[8];
    int h = r >> 10, t = r & (TT - 1);
    int kcnt = (t >> 8) + 1;
    float v = 0.f;
    for (int kz = 0; kz < kcnt; kz++)
        v += g_part[(size_t)(h * 4 + kz) * TT * DD + (size_t)t * DD + d];
    float2 mv = meanvar192(v, s1, s2);
    g_ykv[(size_t)r * DD + d] = h1((v - mv.x) * rsqrtf(mv.y + 1e-5f));
}

__global__ void finalize_k()
{
    int t = blockIdx.x, d = threadIdx.x;
    __shared__ float s1[8], s2[8];
    float ym = 0.f;
    #pragma unroll
    for (int c = 0; c < KSPLIT; c++)
        ym += g_part[(size_t)c * TT * DD + (size_t)t * DD + d];
    float2 mv = meanvar192(ym, s1, s2);
    float l1 = (ym - mv.x) * rsqrtf(mv.y + 1e-5f);
    float xv = g_x[(size_t)t * DD + d] + l1;
    float2 mv2 = meanvar192(xv, s1, s2);
    float r = (xv - mv2.x) * rsqrtf(mv2.y + 1e-5f);
    g_x [(size_t)t * DD + d] = r;
    g_xr[(size_t)t * DD + d] = h1(r);
    g_xT[(size_t)d * TT + t] = h1(r);
}

// ---------------------------------------------------------------------------
extern "C" void kernel_launch(void* const* d_in, const int* in_sizes, int n_in,
                              void* d_out, int out_size)
{
    const int*   idx  = (const int*)  d_in[0];
    const float* decx = (const float*)d_in[1];
    const float* decy = (const float*)d_in[2];
    const float* enc  = (const float*)d_in[3];
    const float* emb  = (const float*)d_in[4];
    const float* pos  = (const float*)d_in[5];
    const float* lmh  = (const float*)d_in[6];
    float* out = (float*)d_out;

    __half *pxr, *pxT, *pxs, *pqr, *psc, *pykv, *pwdxT, *pwdyT, *pencT, *plmhT;
    float *pscp, *ppart;
    float2* prt;
    cudaGetSymbolAddress((void**)&pxr,   g_xr);
    cudaGetSymbolAddress((void**)&pxT,   g_xT);
    cudaGetSymbolAddress((void**)&pxs,   g_xs);
    cudaGetSymbolAddress((void**)&pqr,   g_qr);
    cudaGetSymbolAddress((void**)&psc,   g_sc);
    cudaGetSymbolAddress((void**)&pscp,  g_scp);
    cudaGetSymbolAddress((void**)&pykv,  g_ykv);
    cudaGetSymbolAddress((void**)&ppart, g_part);
    cudaGetSymbolAddress((void**)&prt,   g_rt);
    cudaGetSymbolAddress((void**)&pwdxT, g_wdxT);
    cudaGetSymbolAddress((void**)&pwdyT, g_wdyT);
    cudaGetSymbolAddress((void**)&pencT, g_encT);
    cudaGetSymbolAddress((void**)&plmhT, g_lmhT);

    const int SMEM1 = NSTAGE * 2 * ST1_H * 2;            // 110592 B
    cudaFuncSetAttribute(gemm_mma<0>, cudaFuncAttributeMaxDynamicSharedMemorySize, SMEM1);
    cudaFuncSetAttribute(gemm_mma<1>, cudaFuncAttributeMaxDynamicSharedMemorySize, SMEM1);
    cudaFuncSetAttribute(gemm_mma<2>, cudaFuncAttributeMaxDynamicSharedMemorySize, SMEM1);
    cudaFuncSetAttribute(gemm_mma<3>, cudaFuncAttributeMaxDynamicSharedMemorySize, SMEM1);
    cudaFuncSetAttribute(gemm_mma<4>, cudaFuncAttributeMaxDynamicSharedMemorySize, SMEM1);
    cudaFuncSetAttribute(gemm_mma<5>, cudaFuncAttributeMaxDynamicSharedMemorySize, SMEM1);

    dim3 tb(32, 8);
    transpose_half_k<<<dim3(NN/32, DD/32, NHH), tb>>>(decx, pwdxT, DD, NN,
                                                      (long long)DD*NN, (long long)NN*DD);
    transpose_half_k<<<dim3(NN/32, DD/32, NHH), tb>>>(decy, pwdyT, DD, NN,
                                                      (long long)DD*NN, (long long)NN*DD);
    transpose_half_k<<<dim3(DD/32, (NHH*NN)/32, 1), tb>>>(enc, pencT, NHH*NN, DD, 0, 0);
    transpose_half_k<<<dim3(VV/32, DD/32, 1), tb>>>(lmh, plmhT, DD, VV, 0, 0);

    sincos_k<<<(TT * (NN / 2) + 255) / 256, 256>>>();
    embed_ln_k<<<TT, 192>>>(idx, emb, pos);

    for (int l = 0; l < NLAYER; l++) {
        // x_sparse(fp16) = relu(x @ decx[h]);  qr(fp16) = rope(fp32 relu)
        gemm_mma<4><<<dim3(NN / 128, TT / 128, NHH), 256, SMEM1>>>(
            pxr, pwdxT, pxs, nullptr, pqr, prt, NN, DD, DD, DD, NN,
            0LL, (long long)NN * DD, (long long)TT * NN);

        // scores partials: lower-triangle tiles, K split in 2 (bz = h*2+ks)
        gemm_mma<3><<<dim3(36, 1, NHH * SCSPLIT), 256, SMEM1>>>(
            pqr, pqr, pscp, nullptr, nullptr, nullptr, TT, NN / SCSPLIT, NN, NN, TT,
            (long long)TT * NN, 0LL, (long long)TT * TT);

        // g_sc(fp16) = tril_mask(p0+p1) [lower triangle only]
        reduce_sc_k<<<NHH * TT * TT / 8 / 256, 256>>>();

        // ykv partials(fp32) = scores @ x   (tri-skip split-K; bz = h*20+j)
        gemm_mma<2><<<dim3(2, 1, NHH * 20), 256, SMEM1>>>(
            psc, pxT, ppart, nullptr, nullptr, nullptr, DD, 256, TT, TT, DD,
            (long long)TT * TT, 0LL, (long long)TT * DD);

        // ykv(fp16) = ln(sum valid partials)
        ln_ykv_k<<<NHH * TT, 192>>>();

        // xy(fp16) = relu(ykv @ decy[h]) * x_sparse(fp16, fp32 math)
        gemm_mma<5><<<dim3(NN / 128, TT / 128, NHH), 256, SMEM1>>>(
            pykv, pwdyT, pqr, pxs, nullptr, nullptr, NN, DD, DD, DD, NN,
            (long long)TT * DD, (long long)NN * DD, (long long)TT * NN);

        // ymlp partials(fp32): xy @ enc^T, split-K = 16
        gemm_mma<1><<<dim3(2, TT / 128, KSPLIT), 256, SMEM1>>>(
            pqr, pencT, ppart, nullptr, nullptr, nullptr, DD, KCH, NN, NHH * NN, DD,
            0LL, (long long)KCH, (long long)TT * DD);

        finalize_k<<<TT, 192>>>();
    }

    // logits(fp32) = x @ lm_head
    gemm_mma<0><<<dim3(2, TT / 128, 1), 256, SMEM1>>>(
        pxr, plmhT, out, nullptr, nullptr, nullptr, VV, DD, DD, DD, VV,
        0LL, 0LL, 0LL);
}